// round 16
// baseline (speedup 1.0000x reference)
#include <cuda_runtime.h>
#include <cuda_fp16.h>
#include <math.h>
#include <stdint.h>

#define T_STEPS 200
#define BATCH   1024
#define XD      48
#define AD      15
#define IN_DIM  64
#define H_DIM   512
#define OUT_DIM 32
#define H1      513
#define KTOT    576        // 64 (x hi) + 512 (h hi)
#define CHUNKS  9          // KTOT / 64
#define NT_CNT  37         // uneven N tiles: 34 x 56 cols + 3 x 48 cols
#define NCTA    148        // 37 nT x 4 mT, one per SM
#define MTGRP   37         // CTAs per mT barrier group

// ---------------- static device scratch ----------------
__device__ __half g_Ax[T_STEPS][BATCH][64];    // x hi per step
__device__ __half g_Ah[2][BATCH][512];         // h hi, double buffered
__device__ __half g_W[2048][KTOT];             // permuted weights, np = hc*4 + gate
__device__ __half g_W1[2][576][512];           // mlp1 weights fp16, zero-padded
__device__ float g_bias[2048];                 // permuted biases, np = hc*4 + gate
__device__ float g_z1[2][BATCH * H1];
__device__ unsigned g_maxm_u;
__device__ unsigned g_count4[4 * 32];          // per-mT barrier counters, 128B apart

// ---------------- helpers ----------------
__device__ __forceinline__ uint32_t smem_u32(const void* p) {
    uint32_t a;
    asm("{ .reg .u64 t; cvta.to.shared.u64 t, %1; cvt.u32.u64 %0, t; }" : "=r"(a) : "l"(p));
    return a;
}
__device__ __forceinline__ uint32_t swz(uint32_t o) { return o ^ ((o >> 3) & 0x70); }
__device__ __forceinline__ void cpa16(uint32_t dst, const void* src) {
    asm volatile("cp.async.cg.shared.global [%0], [%1], 16;"
                 :: "r"(dst), "l"(__cvta_generic_to_global(src)));
}
__device__ __forceinline__ void ldsm4(uint32_t* r, uint32_t addr) {
    asm volatile("ldmatrix.sync.aligned.m8n8.x4.shared.b16 {%0,%1,%2,%3}, [%4];"
                 : "=r"(r[0]), "=r"(r[1]), "=r"(r[2]), "=r"(r[3]) : "r"(addr));
}
__device__ __forceinline__ void ldsm2(uint32_t* r, uint32_t addr) {
    asm volatile("ldmatrix.sync.aligned.m8n8.x2.shared.b16 {%0,%1}, [%2];"
                 : "=r"(r[0]), "=r"(r[1]) : "r"(addr));
}
__device__ __forceinline__ void mma16816(float* d, const uint32_t* a, uint32_t b0, uint32_t b1) {
    asm volatile(
        "mma.sync.aligned.m16n8k16.row.col.f32.f16.f16.f32 "
        "{%0,%1,%2,%3},{%4,%5,%6,%7},{%8,%9},{%0,%1,%2,%3};"
        : "+f"(d[0]), "+f"(d[1]), "+f"(d[2]), "+f"(d[3])
        : "r"(a[0]), "r"(a[1]), "r"(a[2]), "r"(a[3]), "r"(b0), "r"(b1));
}
__device__ __forceinline__ float sgm(float x) {
    return __fdividef(1.0f, 1.0f + __expf(-x));
}
__device__ __forceinline__ float tanh_fast(float x) {
    return 2.0f * __fdividef(1.0f, 1.0f + __expf(-2.0f * x)) - 1.0f;
}

// ---------------- setup kernels ----------------
__global__ __launch_bounds__(256) void zero_kernel() {
    int idx = blockIdx.x * blockDim.x + threadIdx.x;
    int stride = gridDim.x * blockDim.x;
    __half z = __float2half(0.0f);
    for (int i = idx; i < BATCH * 512; i += stride) (&g_Ah[0][0][0])[i] = z;
    if (idx < 4 * 32) g_count4[idx] = 0;
    if (idx == 4 * 32) g_maxm_u = 0u;
}

__global__ __launch_bounds__(256) void maxm_kernel(const float* __restrict__ m) {
    __shared__ float red[256];
    int base = blockIdx.x * 1024;
    float v = 0.0f;
#pragma unroll
    for (int i = 0; i < 4; i++) v = fmaxf(v, m[base + threadIdx.x + i * 256]);
    red[threadIdx.x] = v;
    __syncthreads();
    for (int s = 128; s > 0; s >>= 1) {
        if (threadIdx.x < s) red[threadIdx.x] = fmaxf(red[threadIdx.x], red[threadIdx.x + s]);
        __syncthreads();
    }
    if (threadIdx.x == 0) atomicMax(&g_maxm_u, __float_as_uint(red[0]));
}

// Permuted weights: np = hc*4 + gate  <->  r = gate*512 + hc
__global__ __launch_bounds__(256) void prep_w_kernel(
    const float* __restrict__ w_ih, const float* __restrict__ w_hh,
    const float* __restrict__ b_ih, const float* __restrict__ b_hh)
{
    int np = blockIdx.x;
    int hc = np >> 2;
    int gate = np & 3;
    int r = gate * H_DIM + hc;
    for (int k = threadIdx.x; k < KTOT; k += 256) {
        float v;
        if (k < 64)        v = w_ih[r * IN_DIM + k];
        else               v = w_hh[r * H_DIM + (k - 64)];
        g_W[np][k] = __float2half(v);
    }
    if (threadIdx.x == 0) g_bias[np] = b_ih[r] + b_hh[r];
}

__global__ __launch_bounds__(256) void prep_w1_kernel(
    const float* __restrict__ lw1, const float* __restrict__ vw1)
{
    int n = blockIdx.x;
    int head = blockIdx.y;
    const float* __restrict__ w = head ? vw1 : lw1;
    for (int k = threadIdx.x; k < H_DIM; k += 256)
        g_W1[head][n][k] = (n < H1) ? __float2half(w[n * H_DIM + k]) : __float2half(0.0f);
}

__global__ __launch_bounds__(256) void prep_x_kernel(
    const float* __restrict__ x, const float* __restrict__ a)
{
    int s = blockIdx.x;
    int b = blockIdx.y * 64 + (threadIdx.x >> 2);
    int kb = (threadIdx.x & 3) * 16;
    int trow = T_STEPS - 1 - s;
    __half h[16];
    if (kb < XD) {
        const float4* xr = (const float4*)(x + ((size_t)trow * BATCH + b) * XD + kb);
        float4 v[4];
#pragma unroll
        for (int i = 0; i < 4; i++) v[i] = xr[i];
        const float* vf = (const float*)v;
#pragma unroll
        for (int i = 0; i < 16; i++) h[i] = __float2half(vf[i]);
    } else {
        const float* ar = a + ((size_t)trow * BATCH + b) * AD;
        float tval = (float)s / __uint_as_float(g_maxm_u);
#pragma unroll
        for (int i = 0; i < 15; i++) h[i] = __float2half(ar[i]);
        h[15] = __float2half(tval);
    }
    uint4* dst = (uint4*)&g_Ax[s][b][kb];
    dst[0] = ((uint4*)h)[0];
    dst[1] = ((uint4*)h)[1];
}

// ---------------- persistent LSTM kernel: 148 CTAs, 512 threads ----------------
// smem: B 9 chunks x 7168 B = 64512; A bufs 3 x 32768 = 98304; sH 256*14*4 = 14336.
#define SMEM_B     64512            // 9 * 7168 (1024-aligned chunk stride)
#define ABUF_BYTES 32768
#define NSTAGE_A   3
#define SMEM_SH    (SMEM_B + NSTAGE_A * ABUF_BYTES)
#define SMEM_REQ   (SMEM_SH + 256 * 14 * 4)

__global__ void __launch_bounds__(512, 1) lstm_persistent_kernel()
{
    extern __shared__ char sm[];
    uint32_t sb = smem_u32(sm);

    const int tid = threadIdx.x;
    const int wid = tid >> 5, lane = tid & 31;
    const int nT = blockIdx.x % NT_CNT;
    const int mT = blockIdx.x / NT_CNT;          // 0..3, 256 batch rows each

    const int start_nb = (nT < 34) ? nT * 7 : 238 + (nT - 34) * 6;   // 8-col units
    const bool hasRem = (nT < 34);               // width 7 vs 6 nb
    const int wnb = hasRem ? 7 : 6;
    const int rows = wnb * 8;                    // B rows in this tile
    const int hcStart = start_nb * 2;            // first h-unit of tile

    // ---- prologue: B slice resident in smem ----
    {
        const __half* __restrict__ W = &g_W[start_nb * 8][0];
#pragma unroll
        for (int j = 0; j < CHUNKS; j++) {
            if (tid < rows * 8) {
                int row = tid >> 3, c16 = tid & 7;
                cpa16(sb + j * 7168 + swz(row * 128 + c16 * 16),
                      W + (size_t)row * KTOT + j * 64 + c16 * 8);
            }
        }
        asm volatile("cp.async.commit_group;" ::: "memory");
        asm volatile("cp.async.wait_group 0;" ::: "memory");
        __syncthreads();
    }

    // biases: even lanes own one h-unit per nb -> contiguous float4 (i,f,g,o)
    float4 bq[7];
    if ((lane & 1) == 0) {
#pragma unroll
        for (int nb = 0; nb < 7; nb++) {
            if (nb < wnb) {
                int hc = hcStart + nb * 2 + ((lane >> 1) & 1);
                bq[nb] = *(const float4*)&g_bias[hc * 4];
            }
        }
    }

    float cv[14];                        // cell state (even lanes), 7 nb x 2 rh
#pragma unroll
    for (int e = 0; e < 14; e++) cv[e] = 0.0f;

    const uint32_t abuf0 = sb + SMEM_B;
    const int lrow = lane & 15;
    const uint32_t lcol = (lane >> 4) * 16;
    unsigned* __restrict__ bar = &g_count4[mT * 32];

    // warp-private A issue: warp w stages its rows [16w, 16w+16); buffer j%3
    auto issueW = [&](int s, int j) {
        uint32_t base = abuf0 + (j % NSTAGE_A) * ABUF_BYTES;
        const __half* src_base = (j < 1) ? &g_Ax[s][mT * 256][0] : &g_Ah[s & 1][mT * 256][0];
        int stride = (j < 1) ? 64 : 512;
        int koff = (j < 1) ? 0 : (j - 1) * 64;
#pragma unroll
        for (int i = 0; i < 4; i++) {
            int lin = i * 32 + lane;
            int row = wid * 16 + (lin >> 3), c16 = lin & 7;
            cpa16(base + swz(row * 128 + c16 * 16),
                  src_base + (size_t)row * stride + koff + c16 * 8);
        }
        asm volatile("cp.async.commit_group;" ::: "memory");
    };

    issueW(0, 0);

    for (int s = 0; s < T_STEPS; s++) {
        float acc[7][4];
#pragma unroll
        for (int nb = 0; nb < 7; nb++)
#pragma unroll
            for (int q = 0; q < 4; q++) acc[nb][q] = 0.0f;

        issueW(s, 1);

        for (int j = 0; j < CHUNKS; j++) {
            if (j + 2 < CHUNKS) {
                issueW(s, j + 2);
                asm volatile("cp.async.wait_group 2;" ::: "memory");
            } else if (j + 1 < CHUNKS) {
                asm volatile("cp.async.wait_group 1;" ::: "memory");
            } else {
                asm volatile("cp.async.wait_group 0;" ::: "memory");
            }
            __syncwarp();

            uint32_t Abase = abuf0 + (j % NSTAGE_A) * ABUF_BYTES;
            uint32_t Bbase = sb + j * 7168;
#pragma unroll
            for (int ks = 0; ks < 4; ks++) {
                uint32_t a0[4];
                ldsm4(a0, Abase + swz((wid * 16 + lrow) * 128 + ks * 32 + lcol));
#pragma unroll
                for (int nb4 = 0; nb4 < 3; nb4++) {     // 3 full 16-row groups
                    uint32_t b[4];
                    ldsm4(b, Bbase + swz((nb4 * 16 + lrow) * 128 + ks * 32 + lcol));
                    mma16816(acc[nb4 * 2 + 0], a0, b[0], b[2]);
                    mma16816(acc[nb4 * 2 + 1], a0, b[1], b[3]);
                }
                if (hasRem) {                           // remaining 8 rows (48..55)
                    uint32_t b2[2];
                    ldsm2(b2, Bbase + swz((48 + (lane & 7)) * 128 + ks * 32 +
                                          ((lane >> 3) & 1) * 16));
                    mma16816(acc[6], a0, b2[0], b2[1]);
                }
            }
        }

        if (s + 1 < T_STEPS) issueW(s + 1, 0);

        // ---- epilogue: pair-lane shfl gathers all 4 gates into even lanes ----
        float* sH = (float*)(sm + SMEM_SH);      // [256][14], rows warp-private
#pragma unroll
        for (int nb = 0; nb < 7; nb++) {
            if (nb < wnb) {
#pragma unroll
                for (int rh = 0; rh < 2; rh++) {
                    float gpart = __shfl_xor_sync(0xffffffffu, acc[nb][rh * 2 + 0], 1);
                    float opart = __shfl_xor_sync(0xffffffffu, acc[nb][rh * 2 + 1], 1);
                    if ((lane & 1) == 0) {
                        float iv = sgm(acc[nb][rh * 2 + 0] + bq[nb].x);
                        float fv = sgm(acc[nb][rh * 2 + 1] + bq[nb].y);
                        float gv = tanh_fast(gpart + bq[nb].z);
                        float ov = sgm(opart + bq[nb].w);
                        int e = nb * 2 + rh;
                        float c = fv * cv[e] + iv * gv;
                        cv[e] = c;
                        int row = wid * 16 + (lane >> 2) + rh * 8;
                        int hcl = nb * 2 + ((lane >> 1) & 1);
                        sH[row * 14 + hcl] = ov * tanh_fast(c);
                    }
                }
            }
        }
        __syncwarp();

        // h write: warp-private rows [16w,16w+16), wnb uints (2 h-units) per row
        {
            __half* Aout = &g_Ah[(s + 1) & 1][0][0];
            if (hasRem) {                // wnb = 7 -> 112 uints per warp
#pragma unroll
                for (int it = 0; it < 4; it++) {
                    int lin = it * 32 + lane;
                    if (lin < 112) {
                        int rl = lin / 7, i = lin % 7;
                        int row = wid * 16 + rl;
                        int m = mT * 256 + row;
                        __half h0 = __float2half(sH[row * 14 + i * 2]);
                        __half h1 = __float2half(sH[row * 14 + i * 2 + 1]);
                        uint32_t v = (uint32_t)__half_as_ushort(h0) |
                                     ((uint32_t)__half_as_ushort(h1) << 16);
                        *(uint32_t*)&Aout[(size_t)m * 512 + hcStart + i * 2] = v;
                    }
                }
            } else {                     // wnb = 6 -> 96 uints per warp
#pragma unroll
                for (int it = 0; it < 3; it++) {
                    int lin = it * 32 + lane;
                    // 96 = 3*32, all lanes active
                    int rl = lin / 6, i = lin % 6;
                    int row = wid * 16 + rl;
                    int m = mT * 256 + row;
                    __half h0 = __float2half(sH[row * 14 + i * 2]);
                    __half h1 = __float2half(sH[row * 14 + i * 2 + 1]);
                    uint32_t v = (uint32_t)__half_as_ushort(h0) |
                                 ((uint32_t)__half_as_ushort(h1) << 16);
                    *(uint32_t*)&Aout[(size_t)m * 512 + hcStart + i * 2] = v;
                }
            }
        }

        if (s + 1 < T_STEPS) {
            // ---- per-mT grid barrier: 37 CTAs ----
            __threadfence();
            __syncthreads();
            if (tid == 0) {
                atomicAdd(bar, 1u);
                unsigned target = (unsigned)(s + 1) * MTGRP;
                unsigned v;
                do {
                    asm volatile("ld.acquire.gpu.u32 %0, [%1];"
                                 : "=r"(v) : "l"(bar));
                } while (v < target);
            }
            __syncthreads();
        }
    }
}

// ---------------- mlp1 via fp16 mma ----------------
__global__ void __launch_bounds__(256) mlp1_mma_kernel(
    const float* __restrict__ lb1, const float* __restrict__ vb1)
{
    __shared__ char sm1[49152];
    uint32_t sb = smem_u32(sm1);

    const int tid = threadIdx.x;
    const int wid = tid >> 5, lane = tid & 31;
    const int nT = blockIdx.x, mT = blockIdx.y, head = blockIdx.z;
    const float* __restrict__ b1 = head ? vb1 : lb1;
    const __half* __restrict__ Ah = &g_Ah[0][mT * 128][0];
    const __half* __restrict__ W1 = &g_W1[head][nT * 64][0];
    float* __restrict__ z1 = g_z1[head];

    auto issue = [&](int j) {
        uint32_t base = sb + (j & 1) * 24576;
#pragma unroll
        for (int o = 0; o < 4; o++) {
            int lin = o * 256 + tid;
            int row = lin >> 3, c16 = lin & 7;
            cpa16(base + swz(row * 128 + c16 * 16),
                  Ah + (size_t)row * 512 + j * 64 + c16 * 8);
        }
#pragma unroll
        for (int o = 0; o < 2; o++) {
            int lin = o * 256 + tid;
            int row = lin >> 3, c16 = lin & 7;
            cpa16(base + 16384 + swz(row * 128 + c16 * 16),
                  W1 + (size_t)row * 512 + j * 64 + c16 * 8);
        }
        asm volatile("cp.async.commit_group;" ::: "memory");
    };

    float acc[8][4];
#pragma unroll
    for (int nb = 0; nb < 8; nb++)
#pragma unroll
        for (int q = 0; q < 4; q++) acc[nb][q] = 0.0f;

    const int lrow = lane & 15;
    const uint32_t lcol = (lane >> 4) * 16;

    issue(0);
    for (int j = 0; j < 8; j++) {
        if (j + 1 < 8) {
            issue(j + 1);
            asm volatile("cp.async.wait_group 1;" ::: "memory");
        } else {
            asm volatile("cp.async.wait_group 0;" ::: "memory");
        }
        __syncthreads();
        uint32_t Abase = sb + (j & 1) * 24576;
        uint32_t Bbase = Abase + 16384;
#pragma unroll
        for (int ks = 0; ks < 4; ks++) {
            uint32_t a0[4];
            ldsm4(a0, Abase + swz((wid * 16 + lrow) * 128 + ks * 32 + lcol));
#pragma unroll
            for (int nb4 = 0; nb4 < 4; nb4++) {
                uint32_t b[4];
                ldsm4(b, Bbase + swz((nb4 * 16 + lrow) * 128 + ks * 32 + lcol));
                mma16816(acc[nb4 * 2 + 0], a0, b[0], b[2]);
                mma16816(acc[nb4 * 2 + 1], a0, b[1], b[3]);
            }
        }
        __syncthreads();
    }

#pragma unroll
    for (int nb = 0; nb < 8; nb++) {
        int n = nT * 64 + nb * 8 + 2 * (lane & 3);
#pragma unroll
        for (int t = 0; t < 2; t++) {
            if (n + t < H1) {
                float bvv = b1[n + t];
#pragma unroll
                for (int rh = 0; rh < 2; rh++) {
                    int row = mT * 128 + wid * 16 + (lane >> 2) + rh * 8;
                    z1[row * H1 + n + t] = tanh_fast(acc[nb][rh * 2 + t] + bvv);
                }
            }
        }
    }
}

// ---------------- mlp2 (fp32 SIMT) ----------------
__global__ __launch_bounds__(256) void mlp2_kernel(
    const float* __restrict__ lw2, const float* __restrict__ lb2,
    const float* __restrict__ vw2, const float* __restrict__ vb2,
    float* __restrict__ out)
{
    __shared__ float z1s[32 * 65];
    __shared__ float w2s[32 * 65];
    const int head = blockIdx.y;
    const float* __restrict__ w2 = head ? vw2 : lw2;
    const float* __restrict__ b2 = head ? vb2 : lb2;
    const float* __restrict__ z1 = g_z1[head];
    const int r0 = blockIdx.x * 32;
    const int tid = threadIdx.x, o = tid & 31, rg = tid >> 5;
    float acc[4] = {0.f, 0.f, 0.f, 0.f};
    for (int k0 = 0; k0 < H1; k0 += 64) {
#pragma unroll
        for (int i = 0; i < 8; i++) {
            int lin = tid + i * 256;
            int kk = lin & 63, rr = lin >> 6;
            int k = k0 + kk;
            z1s[rr * 65 + kk] = (k < H1) ? z1[(r0 + rr) * H1 + k] : 0.0f;
            w2s[rr * 65 + kk] = (k < H1) ? w2[rr * H1 + k] : 0.0f;
        }
        __syncthreads();
#pragma unroll
        for (int kk = 0; kk < 64; kk++) {
            float wv = w2s[o * 65 + kk];
#pragma unroll
            for (int r = 0; r < 4; r++) acc[r] += z1s[(rg * 4 + r) * 65 + kk] * wv;
        }
        __syncthreads();
    }
    float bvv = b2[o];
#pragma unroll
    for (int r = 0; r < 4; r++)
        out[(size_t)head * BATCH * OUT_DIM + (r0 + rg * 4 + r) * OUT_DIM + o] = tanhf(acc[r] + bvv);
}

// ---------------- launch ----------------
extern "C" void kernel_launch(void* const* d_in, const int* in_sizes, int n_in,
                              void* d_out, int out_size) {
    const float* x    = (const float*)d_in[0];
    const float* a    = (const float*)d_in[1];
    const float* m    = (const float*)d_in[2];
    const float* w_ih = (const float*)d_in[3];
    const float* w_hh = (const float*)d_in[4];
    const float* b_ih = (const float*)d_in[5];
    const float* b_hh = (const float*)d_in[6];
    const float* lw1  = (const float*)d_in[7];
    const float* lb1  = (const float*)d_in[8];
    const float* lw2  = (const float*)d_in[9];
    const float* lb2  = (const float*)d_in[10];
    const float* vw1  = (const float*)d_in[11];
    const float* vb1  = (const float*)d_in[12];
    const float* vw2  = (const float*)d_in[13];
    const float* vb2  = (const float*)d_in[14];

    cudaFuncSetAttribute(lstm_persistent_kernel,
                         cudaFuncAttributeMaxDynamicSharedMemorySize, SMEM_REQ);

    zero_kernel<<<512, 256>>>();
    maxm_kernel<<<200, 256>>>(m);
    prep_w_kernel<<<2048, 256>>>(w_ih, w_hh, b_ih, b_hh);
    prep_w1_kernel<<<dim3(576, 2), 256>>>(lw1, vw1);
    prep_x_kernel<<<dim3(T_STEPS, 16), 256>>>(x, a);

    lstm_persistent_kernel<<<NCTA, 512, SMEM_REQ>>>();

    mlp1_mma_kernel<<<dim3(9, 8, 2), 256>>>(lb1, vb1);
    mlp2_kernel<<<dim3(32, 2), 256>>>(lw2, lb2, vw2, vb2, (float*)d_out);
}

// round 17
// speedup vs baseline: 1.1948x; 1.1948x over previous
#include <cuda_runtime.h>
#include <cuda_fp16.h>
#include <math.h>
#include <stdint.h>

#define T_STEPS 200
#define BATCH   1024
#define XD      48
#define AD      15
#define IN_DIM  64
#define H_DIM   512
#define OUT_DIM 32
#define H1      513
#define KTOT    576        // 64 (x hi) + 512 (h hi)
#define CHUNKS  9          // KTOT / 64
#define NCTA    128        // 32 nT x 4 mT
#define MTGRP   32         // CTAs per mT barrier group

// ---------------- static device scratch ----------------
__device__ __half g_Ax[T_STEPS][BATCH][64];    // x hi per step
__device__ __half g_Ah[2][BATCH][512];         // h hi, double buffered
__device__ __half g_W[2048][KTOT];             // permuted LSTM weights [Wih|Whh]
__device__ __half g_W1[2][576][512];           // mlp1 weights fp16, zero-padded rows >=513
__device__ float g_bias[2048];                 // permuted b_ih+b_hh
__device__ float g_z1[2][BATCH * H1];
__device__ unsigned g_maxm_u;                  // max(m) bits; NEVER reset (idempotent)
__device__ unsigned g_count4[4 * 32];          // per-mT barrier counters, 128B apart

// ---------------- helpers ----------------
__device__ __forceinline__ uint32_t smem_u32(const void* p) {
    uint32_t a;
    asm("{ .reg .u64 t; cvta.to.shared.u64 t, %1; cvt.u32.u64 %0, t; }" : "=r"(a) : "l"(p));
    return a;
}
__device__ __forceinline__ uint32_t swz(uint32_t o) { return o ^ ((o >> 3) & 0x70); }
__device__ __forceinline__ void cpa16(uint32_t dst, const void* src) {
    asm volatile("cp.async.cg.shared.global [%0], [%1], 16;"
                 :: "r"(dst), "l"(__cvta_generic_to_global(src)));
}
__device__ __forceinline__ void ldsm4(uint32_t* r, uint32_t addr) {
    asm volatile("ldmatrix.sync.aligned.m8n8.x4.shared.b16 {%0,%1,%2,%3}, [%4];"
                 : "=r"(r[0]), "=r"(r[1]), "=r"(r[2]), "=r"(r[3]) : "r"(addr));
}
__device__ __forceinline__ void mma16816(float* d, const uint32_t* a, uint32_t b0, uint32_t b1) {
    asm volatile(
        "mma.sync.aligned.m16n8k16.row.col.f32.f16.f16.f32 "
        "{%0,%1,%2,%3},{%4,%5,%6,%7},{%8,%9},{%0,%1,%2,%3};"
        : "+f"(d[0]), "+f"(d[1]), "+f"(d[2]), "+f"(d[3])
        : "r"(a[0]), "r"(a[1]), "r"(a[2]), "r"(a[3]), "r"(b0), "r"(b1));
}
__device__ __forceinline__ float sgm(float x) {
    return __fdividef(1.0f, 1.0f + __expf(-x));
}
__device__ __forceinline__ float tanh_fast(float x) {
    return 2.0f * __fdividef(1.0f, 1.0f + __expf(-2.0f * x)) - 1.0f;
}

// ---------------- fused init: zero (blocks 0..511) + maxm (blocks 512..711) ----
__global__ __launch_bounds__(256) void init_kernel(const float* __restrict__ m) {
    int bid = blockIdx.x;
    if (bid < 512) {
        int idx = bid * 256 + threadIdx.x;
        int stride = 512 * 256;
        __half z = __float2half(0.0f);
        for (int i = idx; i < BATCH * 512; i += stride) (&g_Ah[0][0][0])[i] = z;
        if (idx < 4 * 32) g_count4[idx] = 0;
        // g_maxm_u intentionally NOT reset: atomicMax of a deterministic value
        // is idempotent across graph replays (starts at 0 on first launch).
    } else {
        __shared__ float red[256];
        int base = (bid - 512) * 1024;
        float v = 0.0f;
#pragma unroll
        for (int i = 0; i < 4; i++) v = fmaxf(v, m[base + threadIdx.x + i * 256]);
        red[threadIdx.x] = v;
        __syncthreads();
        for (int s = 128; s > 0; s >>= 1) {
            if (threadIdx.x < s) red[threadIdx.x] = fmaxf(red[threadIdx.x], red[threadIdx.x + s]);
            __syncthreads();
        }
        if (threadIdx.x == 0) atomicMax(&g_maxm_u, __float_as_uint(red[0]));
    }
}

// ---------------- fused prep: w (0..2047) | w1 (2048..3199) | x (3200..6399) ----
__global__ __launch_bounds__(256) void prep_all_kernel(
    const float* __restrict__ w_ih, const float* __restrict__ w_hh,
    const float* __restrict__ b_ih, const float* __restrict__ b_hh,
    const float* __restrict__ lw1, const float* __restrict__ vw1,
    const float* __restrict__ x, const float* __restrict__ a)
{
    int bid = blockIdx.x;
    if (bid < 2048) {
        // LSTM weights: np = hb*64 + gate*16 + hc  <->  r = gate*512 + hb*16 + hc
        int np = bid;
        int hb = np >> 6;
        int gate = (np >> 4) & 3;
        int hc = np & 15;
        int r = gate * H_DIM + hb * 16 + hc;
        for (int k = threadIdx.x; k < KTOT; k += 256) {
            float v;
            if (k < 64)        v = w_ih[r * IN_DIM + k];
            else               v = w_hh[r * H_DIM + (k - 64)];
            g_W[np][k] = __float2half(v);
        }
        if (threadIdx.x == 0) g_bias[np] = b_ih[r] + b_hh[r];
    } else if (bid < 3200) {
        // mlp1 weights fp16, padded to 576 rows
        int t = bid - 2048;
        int head = t / 576;
        int n = t % 576;
        const float* __restrict__ w = head ? vw1 : lw1;
        for (int k = threadIdx.x; k < H_DIM; k += 256)
            g_W1[head][n][k] = (n < H1) ? __float2half(w[n * H_DIM + k]) : __float2half(0.0f);
    } else {
        // x hi per step, vectorized float4 loads
        int t = bid - 3200;
        int s = t % T_STEPS;
        int by = t / T_STEPS;            // 0..15
        int b = by * 64 + (threadIdx.x >> 2);
        int kb = (threadIdx.x & 3) * 16;
        int trow = T_STEPS - 1 - s;
        __half h[16];
        if (kb < XD) {                   // kb = 0,16,32 : pure x, 16B-aligned
            const float4* xr = (const float4*)(x + ((size_t)trow * BATCH + b) * XD + kb);
            float4 v[4];
#pragma unroll
            for (int i = 0; i < 4; i++) v[i] = xr[i];
            const float* vf = (const float*)v;
#pragma unroll
            for (int i = 0; i < 16; i++) h[i] = __float2half(vf[i]);
        } else {                         // kb = 48 : whole a row + t
            const float* ar = a + ((size_t)trow * BATCH + b) * AD;
            float tval = (float)s / __uint_as_float(g_maxm_u);
#pragma unroll
            for (int i = 0; i < 15; i++) h[i] = __float2half(ar[i]);
            h[15] = __float2half(tval);
        }
        uint4* dst = (uint4*)&g_Ax[s][b][kb];
        dst[0] = ((uint4*)h)[0];
        dst[1] = ((uint4*)h)[1];
    }
}

// ---------------- persistent LSTM kernel: 512 threads, 16 warps ----------------
#define SMEM_B     73728
#define ABUF_BYTES 32768
#define NSTAGE_A   3
#define SMEM_SH    (SMEM_B + NSTAGE_A * ABUF_BYTES)
#define SMEM_REQ   (SMEM_SH + 256 * 17 * 4)

__global__ void __launch_bounds__(512, 1) lstm_persistent_kernel()
{
    extern __shared__ char sm[];
    uint32_t sb = smem_u32(sm);

    const int tid = threadIdx.x;
    const int wid = tid >> 5, lane = tid & 31;
    const int nT = blockIdx.x & 31;      // 32 N-tiles of 64 (16 hc x 4 gates)
    const int mT = blockIdx.x >> 5;      // 4 M-tiles of 256 batch rows

    // ---- prologue: B slice resident in smem ----
    {
        const __half* __restrict__ W = &g_W[nT * 64][0];
#pragma unroll
        for (int j = 0; j < CHUNKS; j++) {
            int row = tid >> 3, c16 = tid & 7;
            cpa16(sb + j * 8192 + swz(row * 128 + c16 * 16),
                  W + (size_t)row * KTOT + j * 64 + c16 * 8);
        }
        asm volatile("cp.async.commit_group;" ::: "memory");
        asm volatile("cp.async.wait_group 0;" ::: "memory");
        __syncthreads();
    }

    float bv[16];
#pragma unroll
    for (int g = 0; g < 4; g++)
#pragma unroll
        for (int p = 0; p < 2; p++)
#pragma unroll
            for (int t = 0; t < 2; t++)
                bv[g * 4 + p * 2 + t] = g_bias[nT * 64 + g * 16 + p * 8 + 2 * (lane & 3) + t];

    float cv[8];
#pragma unroll
    for (int e = 0; e < 8; e++) cv[e] = 0.0f;

    const uint32_t abuf0 = sb + SMEM_B;
    const int lrow = lane & 15;
    const uint32_t lcol = (lane >> 4) * 16;
    unsigned* __restrict__ bar = &g_count4[mT * 32];

    auto issueW = [&](int s, int j) {
        uint32_t base = abuf0 + (j % NSTAGE_A) * ABUF_BYTES;
        const __half* src_base = (j < 1) ? &g_Ax[s][mT * 256][0] : &g_Ah[s & 1][mT * 256][0];
        int stride = (j < 1) ? 64 : 512;
        int koff = (j < 1) ? 0 : (j - 1) * 64;
#pragma unroll
        for (int i = 0; i < 4; i++) {
            int lin = i * 32 + lane;
            int row = wid * 16 + (lin >> 3), c16 = lin & 7;
            cpa16(base + swz(row * 128 + c16 * 16),
                  src_base + (size_t)row * stride + koff + c16 * 8);
        }
        asm volatile("cp.async.commit_group;" ::: "memory");
    };

    issueW(0, 0);

    for (int s = 0; s < T_STEPS; s++) {
        float acc[8][4];
#pragma unroll
        for (int nb = 0; nb < 8; nb++)
#pragma unroll
            for (int q = 0; q < 4; q++) acc[nb][q] = 0.0f;

        issueW(s, 1);

        for (int j = 0; j < CHUNKS; j++) {
            if (j + 2 < CHUNKS) {
                issueW(s, j + 2);
                asm volatile("cp.async.wait_group 2;" ::: "memory");
            } else if (j + 1 < CHUNKS) {
                asm volatile("cp.async.wait_group 1;" ::: "memory");
            } else {
                asm volatile("cp.async.wait_group 0;" ::: "memory");
            }
            __syncwarp();

            uint32_t Abase = abuf0 + (j % NSTAGE_A) * ABUF_BYTES;
            uint32_t Bbase = sb + j * 8192;
#pragma unroll
            for (int ks = 0; ks < 4; ks++) {
                uint32_t a0[4];
                ldsm4(a0, Abase + swz((wid * 16 + lrow) * 128 + ks * 32 + lcol));
#pragma unroll
                for (int nb4 = 0; nb4 < 4; nb4++) {
                    uint32_t b[4];
                    ldsm4(b, Bbase + swz((nb4 * 16 + lrow) * 128 + ks * 32 + lcol));
                    mma16816(acc[nb4 * 2 + 0], a0, b[0], b[2]);
                    mma16816(acc[nb4 * 2 + 1], a0, b[1], b[3]);
                }
            }
        }

        if (s + 1 < T_STEPS) issueW(s + 1, 0);

        float* sH = (float*)(sm + SMEM_SH);
#pragma unroll
        for (int rh = 0; rh < 2; rh++) {
            int row = wid * 16 + (lane >> 2) + rh * 8;
#pragma unroll
            for (int p = 0; p < 2; p++) {
#pragma unroll
                for (int t = 0; t < 2; t++) {
                    int q = rh * 2 + t;
                    int e = (rh * 2 + p) * 2 + t;
                    float iv = acc[0 + p][q] + bv[0 + p * 2 + t];
                    float fv = acc[2 + p][q] + bv[4 + p * 2 + t];
                    float gv = acc[4 + p][q] + bv[8 + p * 2 + t];
                    float ov = acc[6 + p][q] + bv[12 + p * 2 + t];
                    iv = sgm(iv);
                    fv = sgm(fv);
                    ov = sgm(ov);
                    gv = tanh_fast(gv);
                    float c = fv * cv[e] + iv * gv;
                    cv[e] = c;
                    sH[row * 17 + p * 8 + 2 * (lane & 3) + t] = ov * tanh_fast(c);
                }
            }
        }
        __syncwarp();

        {
            const int r = tid >> 1, half = tid & 1;
            const int m = mT * 256 + r;
            __half hi[8];
#pragma unroll
            for (int i = 0; i < 8; i++)
                hi[i] = __float2half(sH[r * 17 + half * 8 + i]);
            __half* Aout = &g_Ah[(s + 1) & 1][0][0];
            *((uint4*)&Aout[(size_t)m * 512 + nT * 16 + half * 8]) = ((uint4*)hi)[0];
        }

        if (s + 1 < T_STEPS) {
            __threadfence();
            __syncthreads();
            if (tid == 0) {
                atomicAdd(bar, 1u);
                unsigned target = (unsigned)(s + 1) * MTGRP;
                unsigned v;
                do {
                    asm volatile("ld.acquire.gpu.u32 %0, [%1];"
                                 : "=r"(v) : "l"(bar));
                } while (v < target);
            }
            __syncthreads();
        }
    }
}

// ---------------- mlp1 via fp16 mma: z1 = tanh(h @ w1^T + b1) ----------------
// grid (9 nT, 8 mT, 2 head), 256 threads; CTA tile M=128 x N=64; K=512, 8 chunks
__global__ void __launch_bounds__(256) mlp1_mma_kernel(
    const float* __restrict__ lb1, const float* __restrict__ vb1)
{
    __shared__ char sm1[49152];          // 2 x (A 16KB + B 8KB)
    uint32_t sb = smem_u32(sm1);

    const int tid = threadIdx.x;
    const int wid = tid >> 5, lane = tid & 31;
    const int nT = blockIdx.x, mT = blockIdx.y, head = blockIdx.z;
    const float* __restrict__ b1 = head ? vb1 : lb1;
    const __half* __restrict__ Ah = &g_Ah[0][mT * 128][0];     // final h fp16
    const __half* __restrict__ W1 = &g_W1[head][nT * 64][0];
    float* __restrict__ z1 = g_z1[head];

    auto issue = [&](int j) {
        uint32_t base = sb + (j & 1) * 24576;
#pragma unroll
        for (int o = 0; o < 4; o++) {    // A: 128 rows x 128B
            int lin = o * 256 + tid;
            int row = lin >> 3, c16 = lin & 7;
            cpa16(base + swz(row * 128 + c16 * 16),
                  Ah + (size_t)row * 512 + j * 64 + c16 * 8);
        }
#pragma unroll
        for (int o = 0; o < 2; o++) {    // B: 64 rows x 128B
            int lin = o * 256 + tid;
            int row = lin >> 3, c16 = lin & 7;
            cpa16(base + 16384 + swz(row * 128 + c16 * 16),
                  W1 + (size_t)row * 512 + j * 64 + c16 * 8);
        }
        asm volatile("cp.async.commit_group;" ::: "memory");
    };

    float acc[8][4];
#pragma unroll
    for (int nb = 0; nb < 8; nb++)
#pragma unroll
        for (int q = 0; q < 4; q++) acc[nb][q] = 0.0f;

    const int lrow = lane & 15;
    const uint32_t lcol = (lane >> 4) * 16;

    issue(0);
    for (int j = 0; j < 8; j++) {
        if (j + 1 < 8) {
            issue(j + 1);
            asm volatile("cp.async.wait_group 1;" ::: "memory");
        } else {
            asm volatile("cp.async.wait_group 0;" ::: "memory");
        }
        __syncthreads();
        uint32_t Abase = sb + (j & 1) * 24576;
        uint32_t Bbase = Abase + 16384;
#pragma unroll
        for (int ks = 0; ks < 4; ks++) {
            uint32_t a0[4];
            ldsm4(a0, Abase + swz((wid * 16 + lrow) * 128 + ks * 32 + lcol));
#pragma unroll
            for (int nb4 = 0; nb4 < 4; nb4++) {
                uint32_t b[4];
                ldsm4(b, Bbase + swz((nb4 * 16 + lrow) * 128 + ks * 32 + lcol));
                mma16816(acc[nb4 * 2 + 0], a0, b[0], b[2]);
                mma16816(acc[nb4 * 2 + 1], a0, b[1], b[3]);
            }
        }
        __syncthreads();
    }

#pragma unroll
    for (int nb = 0; nb < 8; nb++) {
        int n = nT * 64 + nb * 8 + 2 * (lane & 3);
#pragma unroll
        for (int t = 0; t < 2; t++) {
            if (n + t < H1) {
                float bvv = b1[n + t];
#pragma unroll
                for (int rh = 0; rh < 2; rh++) {
                    int row = mT * 128 + wid * 16 + (lane >> 2) + rh * 8;
                    z1[row * H1 + n + t] = tanh_fast(acc[nb][rh * 2 + t] + bvv);
                }
            }
        }
    }
}

// ---------------- mlp2 (fp32 SIMT) ----------------
__global__ __launch_bounds__(256) void mlp2_kernel(
    const float* __restrict__ lw2, const float* __restrict__ lb2,
    const float* __restrict__ vw2, const float* __restrict__ vb2,
    float* __restrict__ out)
{
    __shared__ float z1s[32 * 65];
    __shared__ float w2s[32 * 65];
    const int head = blockIdx.y;
    const float* __restrict__ w2 = head ? vw2 : lw2;
    const float* __restrict__ b2 = head ? vb2 : lb2;
    const float* __restrict__ z1 = g_z1[head];
    const int r0 = blockIdx.x * 32;
    const int tid = threadIdx.x, o = tid & 31, rg = tid >> 5;
    float acc[4] = {0.f, 0.f, 0.f, 0.f};
    for (int k0 = 0; k0 < H1; k0 += 64) {
#pragma unroll
        for (int i = 0; i < 8; i++) {
            int lin = tid + i * 256;
            int kk = lin & 63, rr = lin >> 6;
            int k = k0 + kk;
            z1s[rr * 65 + kk] = (k < H1) ? z1[(r0 + rr) * H1 + k] : 0.0f;
            w2s[rr * 65 + kk] = (k < H1) ? w2[rr * H1 + k] : 0.0f;
        }
        __syncthreads();
#pragma unroll
        for (int kk = 0; kk < 64; kk++) {
            float wv = w2s[o * 65 + kk];
#pragma unroll
            for (int r = 0; r < 4; r++) acc[r] += z1s[(rg * 4 + r) * 65 + kk] * wv;
        }
        __syncthreads();
    }
    float bvv = b2[o];
#pragma unroll
    for (int r = 0; r < 4; r++)
        out[(size_t)head * BATCH * OUT_DIM + (r0 + rg * 4 + r) * OUT_DIM + o] = tanhf(acc[r] + bvv);
}

// ---------------- launch ----------------
extern "C" void kernel_launch(void* const* d_in, const int* in_sizes, int n_in,
                              void* d_out, int out_size) {
    const float* x    = (const float*)d_in[0];
    const float* a    = (const float*)d_in[1];
    const float* m    = (const float*)d_in[2];
    const float* w_ih = (const float*)d_in[3];
    const float* w_hh = (const float*)d_in[4];
    const float* b_ih = (const float*)d_in[5];
    const float* b_hh = (const float*)d_in[6];
    const float* lw1  = (const float*)d_in[7];
    const float* lb1  = (const float*)d_in[8];
    const float* lw2  = (const float*)d_in[9];
    const float* lb2  = (const float*)d_in[10];
    const float* vw1  = (const float*)d_in[11];
    const float* vb1  = (const float*)d_in[12];
    const float* vw2  = (const float*)d_in[13];
    const float* vb2  = (const float*)d_in[14];

    cudaFuncSetAttribute(lstm_persistent_kernel,
                         cudaFuncAttributeMaxDynamicSharedMemorySize, SMEM_REQ);

    init_kernel<<<712, 256>>>(m);
    prep_all_kernel<<<6400, 256>>>(w_ih, w_hh, b_ih, b_hh, lw1, vw1, x, a);

    lstm_persistent_kernel<<<NCTA, 512, SMEM_REQ>>>();

    mlp1_mma_kernel<<<dim3(9, 8, 2), 256>>>(lb1, vb1);
    mlp2_kernel<<<dim3(32, 2), 256>>>(lw2, lb2, vw2, vb2, (float*)d_out);
}